// round 1
// baseline (speedup 1.0000x reference)
#include <cuda_runtime.h>
#include <cuda_bf16.h>
#include <math.h>

// Problem constants (fixed by the dataset)
#define NMAX 200000
#define EMAX 4000000
#define RREL 4
#define DDIM 64
#define NR   (NMAX * RREL)     // 800000
#define GG   64
#define CC   10

// ---------------- scratch (static __device__, no allocation) ----------------
__device__ int   g_cnt[NR];
__device__ int   g_offs[NR + 1];
__device__ int   g_cursor[NR];
__device__ int   g_csr[EMAX];
__device__ int   g_partial[256];
__device__ float g_hA[(size_t)NMAX * DDIM];
__device__ float g_hB[(size_t)NMAX * DDIM];
__device__ float g_Z[(size_t)NMAX * (RREL * DDIM)];
__device__ float g_pooled[GG * DDIM];

// ---------------- CSR build ----------------
__global__ void k_zero_cnt() {
    int i = blockIdx.x * blockDim.x + threadIdx.x;
    if (i < NR) g_cnt[i] = 0;
}

__global__ void k_count_edges(const int* __restrict__ tgt,
                              const int* __restrict__ et, int E) {
    int e = blockIdx.x * blockDim.x + threadIdx.x;
    if (e < E) atomicAdd(&g_cnt[tgt[e] * RREL + et[e]], 1);
}

// scan phase 1: per-block exclusive scan of g_cnt -> g_offs, block totals -> g_partial
#define SCAN_T 1024
#define SCAN_E 4096     // 4 per thread
__global__ void k_scan1() {
    __shared__ int sdata[SCAN_T];
    int b = blockIdx.x, t = threadIdx.x;
    int base = b * SCAN_E + t * 4;
    int v0 = (base + 0 < NR) ? g_cnt[base + 0] : 0;
    int v1 = (base + 1 < NR) ? g_cnt[base + 1] : 0;
    int v2 = (base + 2 < NR) ? g_cnt[base + 2] : 0;
    int v3 = (base + 3 < NR) ? g_cnt[base + 3] : 0;
    int tot = v0 + v1 + v2 + v3;
    sdata[t] = tot;
    __syncthreads();
    for (int off = 1; off < SCAN_T; off <<= 1) {
        int x = (t >= off) ? sdata[t - off] : 0;
        __syncthreads();
        sdata[t] += x;
        __syncthreads();
    }
    int excl = sdata[t] - tot;
    if (base + 0 < NR) g_offs[base + 0] = excl;
    if (base + 1 < NR) g_offs[base + 1] = excl + v0;
    if (base + 2 < NR) g_offs[base + 2] = excl + v0 + v1;
    if (base + 3 < NR) g_offs[base + 3] = excl + v0 + v1 + v2;
    if (t == SCAN_T - 1) g_partial[b] = sdata[SCAN_T - 1];
}

// scan phase 2: exclusive scan of block totals (NB <= 256) in one block
__global__ void k_scan2(int NB) {
    __shared__ int sdata[256];
    int t = threadIdx.x;
    int v = (t < NB) ? g_partial[t] : 0;
    sdata[t] = v;
    __syncthreads();
    for (int off = 1; off < 256; off <<= 1) {
        int x = (t >= off) ? sdata[t - off] : 0;
        __syncthreads();
        sdata[t] += x;
        __syncthreads();
    }
    if (t < NB) g_partial[t] = sdata[t] - v;
}

// scan phase 3: add block offsets; init cursor; set sentinel
__global__ void k_scan3(int E) {
    int b = blockIdx.x, t = threadIdx.x;
    int add = g_partial[b];
    int base = b * SCAN_E + t * 4;
    #pragma unroll
    for (int i = 0; i < 4; i++) {
        int idx = base + i;
        if (idx < NR) {
            int val = g_offs[idx] + add;
            g_offs[idx] = val;
            g_cursor[idx] = val;
        }
    }
    if (b == 0 && t == 0) g_offs[NR] = E;
}

__global__ void k_fill_edges(const int* __restrict__ src,
                             const int* __restrict__ tgt,
                             const int* __restrict__ et, int E) {
    int e = blockIdx.x * blockDim.x + threadIdx.x;
    if (e < E) {
        int p = atomicAdd(&g_cursor[tgt[e] * RREL + et[e]], 1);
        g_csr[p] = src[e];
    }
}

// ---------------- node embedding ----------------
__global__ void k_embed(const int* __restrict__ x_op, const int* __restrict__ x_cat,
                        const float* __restrict__ op_emb, const float* __restrict__ cat_emb,
                        float* __restrict__ h, int n) {
    int i = blockIdx.x * blockDim.x + threadIdx.x;
    int total = n * DDIM;
    if (i < total) {
        int node = i >> 6, d = i & 63;
        h[i] = op_emb[x_op[node] * DDIM + d] + cat_emb[x_cat[node] * DDIM + d];
    }
}

// ---------------- per-layer aggregation: Z[n][r*64+d] = mean over incoming ----------------
__global__ void k_agg(const float* __restrict__ hin, int n) {
    int warp = (blockIdx.x * blockDim.x + threadIdx.x) >> 5;
    int lane = threadIdx.x & 31;
    if (warp >= n) return;
    int node = warp;
    size_t zbase = (size_t)node * (RREL * DDIM);
    #pragma unroll
    for (int r = 0; r < RREL; r++) {
        int s  = g_offs[node * RREL + r];
        int e2 = g_offs[node * RREL + r + 1];
        float a0 = 0.f, a1 = 0.f;
        for (int j = s; j < e2; j++) {
            int sn = g_csr[j];
            const float* hp = hin + (size_t)sn * DDIM;
            a0 += hp[lane];
            a1 += hp[lane + 32];
        }
        int cnt = e2 - s;
        float inv = (cnt > 0) ? (1.f / (float)cnt) : 0.f;
        g_Z[zbase + r * DDIM + lane]      = a0 * inv;
        g_Z[zbase + r * DDIM + 32 + lane] = a1 * inv;
    }
}

// ---------------- layer GEMM: out[n][e] = Z[n][0:256]@w + h[n]@root + b ----------------
__global__ void k_gemm(const float* __restrict__ hin,
                       const float* __restrict__ w,    // [256][64] = stacked w[r]
                       const float* __restrict__ root, // [64][64]
                       const float* __restrict__ bias, // [64]
                       float* __restrict__ hout,
                       int n, int doRelu) {
    __shared__ float As[32][68];  // As[k][row], padded (68*4=272B rows, 16B aligned)
    __shared__ float Bs[32][64];
    int n0 = blockIdx.x * 64;
    int tx = threadIdx.x & 15, ty = threadIdx.x >> 4;
    float acc[4][4];
    #pragma unroll
    for (int i = 0; i < 4; i++)
        #pragma unroll
        for (int j = 0; j < 4; j++) acc[i][j] = 0.f;

    for (int kt = 0; kt < 10; kt++) {
        const float* Aptr; int lda, kbase; const float* Bptr;
        if (kt < 8) { Aptr = g_Z;  lda = 256; kbase = kt * 32;      Bptr = w    + kt * 32 * 64; }
        else        { Aptr = hin;  lda = 64;  kbase = (kt - 8) * 32; Bptr = root + (kt - 8) * 32 * 64; }
        // load A tile (64 rows x 32 k) transposed into As[k][row]
        for (int i = threadIdx.x; i < 64 * 32; i += 256) {
            int r = i >> 5, c = i & 31;
            int row = n0 + r;
            As[c][r] = (row < n) ? Aptr[(size_t)row * lda + kbase + c] : 0.f;
        }
        // load B tile (32 k x 64 cols)
        for (int i = threadIdx.x; i < 32 * 64; i += 256) {
            int kb = i >> 6, c = i & 63;
            Bs[kb][c] = Bptr[kb * 64 + c];
        }
        __syncthreads();
        #pragma unroll
        for (int kk = 0; kk < 32; kk++) {
            float4 a = *(const float4*)&As[kk][ty * 4];
            float4 b = *(const float4*)&Bs[kk][tx * 4];
            acc[0][0] += a.x * b.x; acc[0][1] += a.x * b.y; acc[0][2] += a.x * b.z; acc[0][3] += a.x * b.w;
            acc[1][0] += a.y * b.x; acc[1][1] += a.y * b.y; acc[1][2] += a.y * b.z; acc[1][3] += a.y * b.w;
            acc[2][0] += a.z * b.x; acc[2][1] += a.z * b.y; acc[2][2] += a.z * b.z; acc[2][3] += a.z * b.w;
            acc[3][0] += a.w * b.x; acc[3][1] += a.w * b.y; acc[3][2] += a.w * b.z; acc[3][3] += a.w * b.w;
        }
        __syncthreads();
    }
    #pragma unroll
    for (int i = 0; i < 4; i++) {
        int row = n0 + ty * 4 + i;
        if (row >= n) continue;
        #pragma unroll
        for (int j = 0; j < 4; j++) {
            int col = tx * 4 + j;
            float v = acc[i][j] + bias[col];
            if (doRelu) v = fmaxf(v, 0.f);
            hout[(size_t)row * DDIM + col] = v;
        }
    }
}

// ---------------- pooling (batch is sorted) ----------------
__device__ __forceinline__ int dev_lower_bound(const int* a, int n, int key) {
    int lo = 0, hi = n;
    while (lo < hi) { int mid = (lo + hi) >> 1; if (a[mid] < key) lo = mid + 1; else hi = mid; }
    return lo;
}

__global__ void k_pool(const float* __restrict__ h, const int* __restrict__ batch, int n) {
    int g = blockIdx.x;
    int lo = dev_lower_bound(batch, n, g);
    int hi = dev_lower_bound(batch, n, g + 1);
    __shared__ float sacc[4][64];
    int d = threadIdx.x & 63, part = threadIdx.x >> 6;
    float s = 0.f;
    for (int i = lo + part; i < hi; i += 4) s += h[(size_t)i * DDIM + d];
    sacc[part][d] = s;
    __syncthreads();
    if (part == 0) {
        float tot = sacc[0][d] + sacc[1][d] + sacc[2][d] + sacc[3][d];
        float c = (float)(hi - lo);
        g_pooled[g * DDIM + d] = tot / fmaxf(c, 1.f);
    }
}

// ---------------- MLP head + log_softmax (one block, thread = graph) ----------------
__global__ void k_head(const float* __restrict__ fc1w, const float* __restrict__ fc1b,
                       const float* __restrict__ fc2w, const float* __restrict__ fc2b,
                       float* __restrict__ out) {
    __shared__ float w1s[64 * 64];
    for (int i = threadIdx.x; i < 64 * 64; i += 64) w1s[i] = fc1w[i];
    __syncthreads();
    int g = threadIdx.x;
    float p[64];
    #pragma unroll
    for (int d = 0; d < 64; d++) p[d] = g_pooled[g * 64 + d];
    float hid[64];
    #pragma unroll 4
    for (int e = 0; e < 64; e++) {
        float s = fc1b[e];
        #pragma unroll
        for (int d = 0; d < 64; d++) s += p[d] * w1s[d * 64 + e];
        hid[e] = fmaxf(s, 0.f);
    }
    float lg[CC];
    #pragma unroll
    for (int c = 0; c < CC; c++) {
        float s = fc2b[c];
        #pragma unroll 4
        for (int e = 0; e < 64; e++) s += hid[e] * fc2w[e * CC + c];
        lg[c] = s;
    }
    float m = lg[0];
    #pragma unroll
    for (int c = 1; c < CC; c++) m = fmaxf(m, lg[c]);
    float sum = 0.f;
    #pragma unroll
    for (int c = 0; c < CC; c++) sum += expf(lg[c] - m);
    float lse = logf(sum);
    #pragma unroll
    for (int c = 0; c < CC; c++) out[g * CC + c] = lg[c] - m - lse;
}

// ---------------- launch ----------------
extern "C" void kernel_launch(void* const* d_in, const int* in_sizes, int n_in,
                              void* d_out, int out_size) {
    const int*   x_op    = (const int*)  d_in[0];
    const int*   x_cat   = (const int*)  d_in[1];
    const int*   eidx    = (const int*)  d_in[2];
    const int*   etype   = (const int*)  d_in[3];
    const int*   batch   = (const int*)  d_in[4];
    const float* op_emb  = (const float*)d_in[5];
    const float* cat_emb = (const float*)d_in[6];
    const float* w1 = (const float*)d_in[7],  *r1 = (const float*)d_in[8],  *b1 = (const float*)d_in[9];
    const float* w2 = (const float*)d_in[10], *r2 = (const float*)d_in[11], *b2 = (const float*)d_in[12];
    const float* w3 = (const float*)d_in[13], *r3 = (const float*)d_in[14], *b3 = (const float*)d_in[15];
    const float* fc1w = (const float*)d_in[16], *fc1b = (const float*)d_in[17];
    const float* fc2w = (const float*)d_in[18], *fc2b = (const float*)d_in[19];
    float* out = (float*)d_out;

    int n = in_sizes[0];
    int E = in_sizes[3];
    const int* src = eidx;
    const int* tgt = eidx + E;

    float* hA;  cudaGetSymbolAddress((void**)&hA, g_hA);
    float* hB;  cudaGetSymbolAddress((void**)&hB, g_hB);

    int NB = (NR + SCAN_E - 1) / SCAN_E;  // 196

    // CSR build (reused across all 3 layers)
    k_zero_cnt<<<(NR + 255) / 256, 256>>>();
    k_count_edges<<<(E + 255) / 256, 256>>>(tgt, etype, E);
    k_scan1<<<NB, SCAN_T>>>();
    k_scan2<<<1, 256>>>(NB);
    k_scan3<<<NB, SCAN_T>>>(E);
    k_fill_edges<<<(E + 255) / 256, 256>>>(src, tgt, etype, E);

    // embedding
    k_embed<<<(n * DDIM + 255) / 256, 256>>>(x_op, x_cat, op_emb, cat_emb, hA, n);

    int aggBlocks  = (n + 7) / 8;        // 8 warps (nodes) per 256-thread block
    int gemmBlocks = (n + 63) / 64;

    // layer 1: hA -> hB (relu)
    k_agg<<<aggBlocks, 256>>>(hA, n);
    k_gemm<<<gemmBlocks, 256>>>(hA, w1, r1, b1, hB, n, 1);
    // layer 2: hB -> hA (relu)
    k_agg<<<aggBlocks, 256>>>(hB, n);
    k_gemm<<<gemmBlocks, 256>>>(hB, w2, r2, b2, hA, n, 1);
    // layer 3: hA -> hB (no relu)
    k_agg<<<aggBlocks, 256>>>(hA, n);
    k_gemm<<<gemmBlocks, 256>>>(hA, w3, r3, b3, hB, n, 0);

    // pool + head
    k_pool<<<GG, 256>>>(hB, batch, n);
    k_head<<<1, 64>>>(fc1w, fc1b, fc2w, fc2b, out);
}

// round 2
// speedup vs baseline: 1.5674x; 1.5674x over previous
#include <cuda_runtime.h>
#include <cuda_bf16.h>
#include <math.h>
#include <stdint.h>

// Problem constants (fixed by the dataset)
#define NMAX 200000
#define EMAX 4000000
#define RREL 4
#define DDIM 64
#define NR   (NMAX * RREL)     // 800000
#define GG   64
#define CC   10

// ---------------- scratch (static __device__, no allocation) ----------------
__device__ int   g_cnt[NR];
__device__ int   g_offs[NR + 1];
__device__ int   g_cursor[NR];
__device__ int   g_csr[EMAX];
__device__ int   g_partial[256];
__device__ float g_hA[(size_t)NMAX * DDIM];
__device__ float g_hB[(size_t)NMAX * DDIM];
__device__ float g_Z[(size_t)NMAX * (RREL * DDIM)];
__device__ float g_pooled[GG * DDIM];

// ---------------- CSR build ----------------
__global__ void k_zero_cnt() {
    int i = blockIdx.x * blockDim.x + threadIdx.x;
    if (i < NR) g_cnt[i] = 0;
}

__global__ void k_count_edges(const int* __restrict__ tgt,
                              const int* __restrict__ et, int E) {
    int e = blockIdx.x * blockDim.x + threadIdx.x;
    if (e < E) atomicAdd(&g_cnt[tgt[e] * RREL + et[e]], 1);
}

#define SCAN_T 1024
#define SCAN_E 4096     // 4 per thread
__global__ void k_scan1() {
    __shared__ int sdata[SCAN_T];
    int b = blockIdx.x, t = threadIdx.x;
    int base = b * SCAN_E + t * 4;
    int v0 = (base + 0 < NR) ? g_cnt[base + 0] : 0;
    int v1 = (base + 1 < NR) ? g_cnt[base + 1] : 0;
    int v2 = (base + 2 < NR) ? g_cnt[base + 2] : 0;
    int v3 = (base + 3 < NR) ? g_cnt[base + 3] : 0;
    int tot = v0 + v1 + v2 + v3;
    sdata[t] = tot;
    __syncthreads();
    for (int off = 1; off < SCAN_T; off <<= 1) {
        int x = (t >= off) ? sdata[t - off] : 0;
        __syncthreads();
        sdata[t] += x;
        __syncthreads();
    }
    int excl = sdata[t] - tot;
    if (base + 0 < NR) g_offs[base + 0] = excl;
    if (base + 1 < NR) g_offs[base + 1] = excl + v0;
    if (base + 2 < NR) g_offs[base + 2] = excl + v0 + v1;
    if (base + 3 < NR) g_offs[base + 3] = excl + v0 + v1 + v2;
    if (t == SCAN_T - 1) g_partial[b] = sdata[SCAN_T - 1];
}

__global__ void k_scan2(int NB) {
    __shared__ int sdata[256];
    int t = threadIdx.x;
    int v = (t < NB) ? g_partial[t] : 0;
    sdata[t] = v;
    __syncthreads();
    for (int off = 1; off < 256; off <<= 1) {
        int x = (t >= off) ? sdata[t - off] : 0;
        __syncthreads();
        sdata[t] += x;
        __syncthreads();
    }
    if (t < NB) g_partial[t] = sdata[t] - v;
}

__global__ void k_scan3(int E) {
    int b = blockIdx.x, t = threadIdx.x;
    int add = g_partial[b];
    int base = b * SCAN_E + t * 4;
    #pragma unroll
    for (int i = 0; i < 4; i++) {
        int idx = base + i;
        if (idx < NR) {
            int val = g_offs[idx] + add;
            g_offs[idx] = val;
            g_cursor[idx] = val;
        }
    }
    if (b == 0 && t == 0) g_offs[NR] = E;
}

__global__ void k_fill_edges(const int* __restrict__ src,
                             const int* __restrict__ tgt,
                             const int* __restrict__ et, int E) {
    int e = blockIdx.x * blockDim.x + threadIdx.x;
    if (e < E) {
        int p = atomicAdd(&g_cursor[tgt[e] * RREL + et[e]], 1);
        g_csr[p] = src[e];
    }
}

// ---------------- node embedding ----------------
__global__ void k_embed(const int* __restrict__ x_op, const int* __restrict__ x_cat,
                        const float* __restrict__ op_emb, const float* __restrict__ cat_emb,
                        float* __restrict__ h, int n) {
    int i = blockIdx.x * blockDim.x + threadIdx.x;
    int total = n * DDIM;
    if (i < total) {
        int node = i >> 6, d = i & 63;
        h[i] = op_emb[x_op[node] * DDIM + d] + cat_emb[x_cat[node] * DDIM + d];
    }
}

// ---------------- per-layer aggregation: Z[n][r*64+d] = mean over incoming ----------------
__global__ void k_agg(const float* __restrict__ hin, int n) {
    int warp = (blockIdx.x * blockDim.x + threadIdx.x) >> 5;
    int lane = threadIdx.x & 31;
    if (warp >= n) return;
    int node = warp;
    size_t zbase = (size_t)node * (RREL * DDIM);
    #pragma unroll
    for (int r = 0; r < RREL; r++) {
        int s  = g_offs[node * RREL + r];
        int e2 = g_offs[node * RREL + r + 1];
        float a0 = 0.f, a1 = 0.f;
        #pragma unroll 4
        for (int j = s; j < e2; j++) {
            int sn = __ldg(&g_csr[j]);
            const float* hp = hin + (size_t)sn * DDIM;
            a0 += __ldg(&hp[lane]);
            a1 += __ldg(&hp[lane + 32]);
        }
        int cnt = e2 - s;
        float inv = (cnt > 0) ? (1.f / (float)cnt) : 0.f;
        g_Z[zbase + r * DDIM + lane]      = a0 * inv;
        g_Z[zbase + r * DDIM + 32 + lane] = a1 * inv;
    }
}

// ---------------- tf32 tensor-core layer GEMM ----------------
// out[n][64] = Z[n][0:256] @ w(256x64)  +  h[n][0:64] @ root(64x64)  + bias
// Block: 256 threads (8 warps), tile M=128, N=64, K looped in 10 chunks of 32.

__device__ __forceinline__ float f2tf32(float x) {
    uint32_t u;
    asm("cvt.rna.tf32.f32 %0, %1;" : "=r"(u) : "f"(x));
    return __uint_as_float(u);
}

__device__ __forceinline__ void mma_tf32(float* d,
                                         uint32_t a0, uint32_t a1, uint32_t a2, uint32_t a3,
                                         uint32_t b0, uint32_t b1) {
    asm volatile(
        "mma.sync.aligned.m16n8k8.row.col.f32.tf32.tf32.f32 "
        "{%0,%1,%2,%3}, {%4,%5,%6,%7}, {%8,%9}, {%0,%1,%2,%3};\n"
        : "+f"(d[0]), "+f"(d[1]), "+f"(d[2]), "+f"(d[3])
        : "r"(a0), "r"(a1), "r"(a2), "r"(a3), "r"(b0), "r"(b1));
}

#define AS_STRIDE 36   // bank = (4m + k) % 32 -> conflict-free fragment loads
#define BS_STRIDE 72   // bank = (8k + n) % 32 -> conflict-free fragment loads

__global__ __launch_bounds__(256) void k_gemm_tc(
        const float* __restrict__ hin,
        const float* __restrict__ w,    // [256][64] stacked per-relation
        const float* __restrict__ root, // [64][64]
        const float* __restrict__ bias, // [64]
        float* __restrict__ hout,
        int n, int doRelu) {
    __shared__ float As[128 * AS_STRIDE];  // [m][k], m=0..127, k=0..31
    __shared__ float Bs[32 * BS_STRIDE];   // [k][n], k=0..31, n=0..63

    int n0   = blockIdx.x * 128;
    int tid  = threadIdx.x;
    int warp = tid >> 5, lane = tid & 31;
    int gr = lane >> 2, ct = lane & 3;
    int warpM = warp * 16;

    float acc[8][4];
    #pragma unroll
    for (int i = 0; i < 8; i++)
        #pragma unroll
        for (int j = 0; j < 4; j++) acc[i][j] = 0.f;

    for (int kt = 0; kt < 10; kt++) {
        const float* Aptr; int lda, kb; const float* Bptr;
        if (kt < 8) { Aptr = g_Z; lda = 256; kb = kt * 32;       Bptr = w    + kt * 2048; }
        else        { Aptr = hin; lda = 64;  kb = (kt - 8) * 32; Bptr = root + (kt - 8) * 2048; }

        // A tile: 128 rows x 32 k = 1024 float4s, 4 per thread
        #pragma unroll
        for (int it = 0; it < 4; it++) {
            int i = tid + it * 256;          // float4 index
            int r = i >> 3, c4 = i & 7;
            int row = n0 + r;
            float4 v = make_float4(0.f, 0.f, 0.f, 0.f);
            if (row < n) v = *(const float4*)&Aptr[(size_t)row * lda + kb + c4 * 4];
            v.x = f2tf32(v.x); v.y = f2tf32(v.y); v.z = f2tf32(v.z); v.w = f2tf32(v.w);
            *(float4*)&As[r * AS_STRIDE + c4 * 4] = v;
        }
        // B tile: 32 k x 64 n = 512 float4s, 2 per thread
        #pragma unroll
        for (int it = 0; it < 2; it++) {
            int i = tid + it * 256;
            int r = i >> 4, c4 = i & 15;
            float4 v = *(const float4*)&Bptr[r * 64 + c4 * 4];
            v.x = f2tf32(v.x); v.y = f2tf32(v.y); v.z = f2tf32(v.z); v.w = f2tf32(v.w);
            *(float4*)&Bs[r * BS_STRIDE + c4 * 4] = v;
        }
        __syncthreads();

        #pragma unroll
        for (int k8 = 0; k8 < 4; k8++) {
            int k0 = k8 * 8;
            uint32_t a0 = __float_as_uint(As[(warpM + gr)     * AS_STRIDE + k0 + ct]);
            uint32_t a1 = __float_as_uint(As[(warpM + gr + 8) * AS_STRIDE + k0 + ct]);
            uint32_t a2 = __float_as_uint(As[(warpM + gr)     * AS_STRIDE + k0 + ct + 4]);
            uint32_t a3 = __float_as_uint(As[(warpM + gr + 8) * AS_STRIDE + k0 + ct + 4]);
            #pragma unroll
            for (int nt = 0; nt < 8; nt++) {
                uint32_t b0 = __float_as_uint(Bs[(k0 + ct)     * BS_STRIDE + nt * 8 + gr]);
                uint32_t b1 = __float_as_uint(Bs[(k0 + ct + 4) * BS_STRIDE + nt * 8 + gr]);
                mma_tf32(acc[nt], a0, a1, a2, a3, b0, b1);
            }
        }
        __syncthreads();
    }

    // epilogue: bias, relu, store (each thread: 2 rows x 8 col-pairs)
    int r0 = n0 + warpM + gr;
    int r1 = r0 + 8;
    #pragma unroll
    for (int nt = 0; nt < 8; nt++) {
        int col = nt * 8 + 2 * ct;
        float bb0 = bias[col], bb1 = bias[col + 1];
        float v00 = acc[nt][0] + bb0, v01 = acc[nt][1] + bb1;
        float v10 = acc[nt][2] + bb0, v11 = acc[nt][3] + bb1;
        if (doRelu) {
            v00 = fmaxf(v00, 0.f); v01 = fmaxf(v01, 0.f);
            v10 = fmaxf(v10, 0.f); v11 = fmaxf(v11, 0.f);
        }
        if (r0 < n) *(float2*)&hout[(size_t)r0 * DDIM + col] = make_float2(v00, v01);
        if (r1 < n) *(float2*)&hout[(size_t)r1 * DDIM + col] = make_float2(v10, v11);
    }
}

// ---------------- pooling (batch is sorted) ----------------
__device__ __forceinline__ int dev_lower_bound(const int* a, int n, int key) {
    int lo = 0, hi = n;
    while (lo < hi) { int mid = (lo + hi) >> 1; if (a[mid] < key) lo = mid + 1; else hi = mid; }
    return lo;
}

__global__ void k_pool(const float* __restrict__ h, const int* __restrict__ batch, int n) {
    int g = blockIdx.x;
    int lo = dev_lower_bound(batch, n, g);
    int hi = dev_lower_bound(batch, n, g + 1);
    __shared__ float sacc[4][64];
    int d = threadIdx.x & 63, part = threadIdx.x >> 6;
    float s = 0.f;
    for (int i = lo + part; i < hi; i += 4) s += h[(size_t)i * DDIM + d];
    sacc[part][d] = s;
    __syncthreads();
    if (part == 0) {
        float tot = sacc[0][d] + sacc[1][d] + sacc[2][d] + sacc[3][d];
        float c = (float)(hi - lo);
        g_pooled[g * DDIM + d] = tot / fmaxf(c, 1.f);
    }
}

// ---------------- MLP head + log_softmax ----------------
__global__ void k_head(const float* __restrict__ fc1w, const float* __restrict__ fc1b,
                       const float* __restrict__ fc2w, const float* __restrict__ fc2b,
                       float* __restrict__ out) {
    __shared__ float w1s[64 * 64];
    for (int i = threadIdx.x; i < 64 * 64; i += 64) w1s[i] = fc1w[i];
    __syncthreads();
    int g = threadIdx.x;
    float p[64];
    #pragma unroll
    for (int d = 0; d < 64; d++) p[d] = g_pooled[g * 64 + d];
    float hid[64];
    #pragma unroll 4
    for (int e = 0; e < 64; e++) {
        float s = fc1b[e];
        #pragma unroll
        for (int d = 0; d < 64; d++) s += p[d] * w1s[d * 64 + e];
        hid[e] = fmaxf(s, 0.f);
    }
    float lg[CC];
    #pragma unroll
    for (int c = 0; c < CC; c++) {
        float s = fc2b[c];
        #pragma unroll 4
        for (int e = 0; e < 64; e++) s += hid[e] * fc2w[e * CC + c];
        lg[c] = s;
    }
    float m = lg[0];
    #pragma unroll
    for (int c = 1; c < CC; c++) m = fmaxf(m, lg[c]);
    float sum = 0.f;
    #pragma unroll
    for (int c = 0; c < CC; c++) sum += expf(lg[c] - m);
    float lse = logf(sum);
    #pragma unroll
    for (int c = 0; c < CC; c++) out[g * CC + c] = lg[c] - m - lse;
}

// ---------------- launch ----------------
extern "C" void kernel_launch(void* const* d_in, const int* in_sizes, int n_in,
                              void* d_out, int out_size) {
    const int*   x_op    = (const int*)  d_in[0];
    const int*   x_cat   = (const int*)  d_in[1];
    const int*   eidx    = (const int*)  d_in[2];
    const int*   etype   = (const int*)  d_in[3];
    const int*   batch   = (const int*)  d_in[4];
    const float* op_emb  = (const float*)d_in[5];
    const float* cat_emb = (const float*)d_in[6];
    const float* w1 = (const float*)d_in[7],  *r1 = (const float*)d_in[8],  *b1 = (const float*)d_in[9];
    const float* w2 = (const float*)d_in[10], *r2 = (const float*)d_in[11], *b2 = (const float*)d_in[12];
    const float* w3 = (const float*)d_in[13], *r3 = (const float*)d_in[14], *b3 = (const float*)d_in[15];
    const float* fc1w = (const float*)d_in[16], *fc1b = (const float*)d_in[17];
    const float* fc2w = (const float*)d_in[18], *fc2b = (const float*)d_in[19];
    float* out = (float*)d_out;

    int n = in_sizes[0];
    int E = in_sizes[3];
    const int* src = eidx;
    const int* tgt = eidx + E;

    float* hA;  cudaGetSymbolAddress((void**)&hA, g_hA);
    float* hB;  cudaGetSymbolAddress((void**)&hB, g_hB);

    int NB = (NR + SCAN_E - 1) / SCAN_E;  // 196

    // CSR build (reused across all 3 layers)
    k_zero_cnt<<<(NR + 255) / 256, 256>>>();
    k_count_edges<<<(E + 255) / 256, 256>>>(tgt, etype, E);
    k_scan1<<<NB, SCAN_T>>>();
    k_scan2<<<1, 256>>>(NB);
    k_scan3<<<NB, SCAN_T>>>(E);
    k_fill_edges<<<(E + 255) / 256, 256>>>(src, tgt, etype, E);

    // embedding
    k_embed<<<(n * DDIM + 255) / 256, 256>>>(x_op, x_cat, op_emb, cat_emb, hA, n);

    int aggBlocks  = (n + 7) / 8;          // 8 warps (nodes) per 256-thread block
    int gemmBlocks = (n + 127) / 128;

    // layer 1: hA -> hB (relu)
    k_agg<<<aggBlocks, 256>>>(hA, n);
    k_gemm_tc<<<gemmBlocks, 256>>>(hA, w1, r1, b1, hB, n, 1);
    // layer 2: hB -> hA (relu)
    k_agg<<<aggBlocks, 256>>>(hB, n);
    k_gemm_tc<<<gemmBlocks, 256>>>(hB, w2, r2, b2, hA, n, 1);
    // layer 3: hA -> hB (no relu)
    k_agg<<<aggBlocks, 256>>>(hA, n);
    k_gemm_tc<<<gemmBlocks, 256>>>(hA, w3, r3, b3, hB, n, 0);

    // pool + head
    k_pool<<<GG, 256>>>(hB, batch, n);
    k_head<<<1, 64>>>(fc1w, fc1b, fc2w, fc2b, out);
}

// round 3
// speedup vs baseline: 1.8582x; 1.1855x over previous
#include <cuda_runtime.h>
#include <cuda_bf16.h>
#include <math.h>
#include <stdint.h>

// Problem constants (fixed by the dataset)
#define NMAX 200000
#define EMAX 4000000
#define RREL 4
#define DDIM 64
#define NR   (NMAX * RREL)     // 800000
#define GG   64
#define CC   10

// ---------------- scratch (static __device__, no allocation) ----------------
__device__ int      g_cnt[NR];
__device__ int      g_offs[NR + 1];
__device__ int      g_cursor[NR];
__device__ int      g_csr[EMAX];
__device__ int      g_partial[256];
__device__ uint32_t g_hA[(size_t)NMAX * 32];          // bf16x2 packed, 64 dims/node
__device__ uint32_t g_hB[(size_t)NMAX * 32];
__device__ uint32_t g_Zp[(size_t)NMAX * 128];         // bf16x2 packed, 256 cols/node
__device__ uint32_t g_Wpk[3][160 * 64];               // packed bf16x2 weights: [k2][n]
__device__ float    g_pooled[GG * DDIM];

// ---------------- CSR build ----------------
__global__ void k_zero_cnt() {
    int i = blockIdx.x * blockDim.x + threadIdx.x;
    if (i < NR) g_cnt[i] = 0;
}

__global__ void k_count_edges(const int* __restrict__ tgt,
                              const int* __restrict__ et, int E) {
    int e = blockIdx.x * blockDim.x + threadIdx.x;
    if (e < E) atomicAdd(&g_cnt[tgt[e] * RREL + et[e]], 1);
}

#define SCAN_T 1024
#define SCAN_E 4096     // 4 per thread
__global__ void k_scan1() {
    __shared__ int sdata[SCAN_T];
    int b = blockIdx.x, t = threadIdx.x;
    int base = b * SCAN_E + t * 4;
    int v0 = (base + 0 < NR) ? g_cnt[base + 0] : 0;
    int v1 = (base + 1 < NR) ? g_cnt[base + 1] : 0;
    int v2 = (base + 2 < NR) ? g_cnt[base + 2] : 0;
    int v3 = (base + 3 < NR) ? g_cnt[base + 3] : 0;
    int tot = v0 + v1 + v2 + v3;
    sdata[t] = tot;
    __syncthreads();
    for (int off = 1; off < SCAN_T; off <<= 1) {
        int x = (t >= off) ? sdata[t - off] : 0;
        __syncthreads();
        sdata[t] += x;
        __syncthreads();
    }
    int excl = sdata[t] - tot;
    if (base + 0 < NR) g_offs[base + 0] = excl;
    if (base + 1 < NR) g_offs[base + 1] = excl + v0;
    if (base + 2 < NR) g_offs[base + 2] = excl + v0 + v1;
    if (base + 3 < NR) g_offs[base + 3] = excl + v0 + v1 + v2;
    if (t == SCAN_T - 1) g_partial[b] = sdata[SCAN_T - 1];
}

__global__ void k_scan2(int NB) {
    __shared__ int sdata[256];
    int t = threadIdx.x;
    int v = (t < NB) ? g_partial[t] : 0;
    sdata[t] = v;
    __syncthreads();
    for (int off = 1; off < 256; off <<= 1) {
        int x = (t >= off) ? sdata[t - off] : 0;
        __syncthreads();
        sdata[t] += x;
        __syncthreads();
    }
    if (t < NB) g_partial[t] = sdata[t] - v;
}

__global__ void k_scan3(int E) {
    int b = blockIdx.x, t = threadIdx.x;
    int add = g_partial[b];
    int base = b * SCAN_E + t * 4;
    #pragma unroll
    for (int i = 0; i < 4; i++) {
        int idx = base + i;
        if (idx < NR) {
            int val = g_offs[idx] + add;
            g_offs[idx] = val;
            g_cursor[idx] = val;
        }
    }
    if (b == 0 && t == 0) g_offs[NR] = E;
}

__global__ void k_fill_edges(const int* __restrict__ src,
                             const int* __restrict__ tgt,
                             const int* __restrict__ et, int E) {
    int e = blockIdx.x * blockDim.x + threadIdx.x;
    if (e < E) {
        int p = atomicAdd(&g_cursor[tgt[e] * RREL + et[e]], 1);
        g_csr[p] = src[e];
    }
}

// ---------------- weight packing: fp32 [k][64] -> bf16x2 pairs [k/2][64] ----------------
// Per layer: rows 0..127 from w (256xK), rows 128..159 from root (64x64).
__global__ void k_pack_weights(const float* __restrict__ w1, const float* __restrict__ r1,
                               const float* __restrict__ w2, const float* __restrict__ r2,
                               const float* __restrict__ w3, const float* __restrict__ r3) {
    int i = blockIdx.x * blockDim.x + threadIdx.x;  // over 3 * 160 * 64
    if (i >= 3 * 160 * 64) return;
    int L = i / (160 * 64);
    int rem = i % (160 * 64);
    int k2 = rem >> 6, nn = rem & 63;
    const float* wp = (L == 0) ? w1 : (L == 1) ? w2 : w3;
    const float* rp = (L == 0) ? r1 : (L == 1) ? r2 : r3;
    float lo, hi;
    if (k2 < 128) { lo = wp[(2 * k2) * 64 + nn];        hi = wp[(2 * k2 + 1) * 64 + nn]; }
    else { int kk = k2 - 128; lo = rp[(2 * kk) * 64 + nn]; hi = rp[(2 * kk + 1) * 64 + nn]; }
    __nv_bfloat162 p = __floats2bfloat162_rn(lo, hi);
    g_Wpk[L][k2 * 64 + nn] = *(uint32_t*)&p;
}

// ---------------- node embedding -> bf16 packed ----------------
__global__ void k_embed(const int* __restrict__ x_op, const int* __restrict__ x_cat,
                        const float* __restrict__ op_emb, const float* __restrict__ cat_emb,
                        uint32_t* __restrict__ h, int n) {
    int i = blockIdx.x * blockDim.x + threadIdx.x;   // n*32 pairs
    if (i < n * 32) {
        int node = i >> 5, dp = i & 31;
        float2 a = *(const float2*)&op_emb[x_op[node] * DDIM + dp * 2];
        float2 b = *(const float2*)&cat_emb[x_cat[node] * DDIM + dp * 2];
        __nv_bfloat162 p = __floats2bfloat162_rn(a.x + b.x, a.y + b.y);
        h[i] = *(uint32_t*)&p;
    }
}

// ---------------- aggregation: Z[n][r*64..] = mean over incoming (bf16 in/out) ----------------
__global__ void k_agg(const uint32_t* __restrict__ hin, int n) {
    int warp = (blockIdx.x * blockDim.x + threadIdx.x) >> 5;
    int lane = threadIdx.x & 31;
    if (warp >= n) return;
    int node = warp;
    size_t zbase = (size_t)node * 128;
    #pragma unroll
    for (int r = 0; r < RREL; r++) {
        int s  = g_offs[node * RREL + r];
        int e2 = g_offs[node * RREL + r + 1];
        float a0 = 0.f, a1 = 0.f;
        int j = s;
        for (; j + 3 < e2; j += 4) {
            int s0 = __ldg(&g_csr[j]), s1 = __ldg(&g_csr[j + 1]);
            int s2 = __ldg(&g_csr[j + 2]), s3 = __ldg(&g_csr[j + 3]);
            uint32_t u0 = __ldg(&hin[(size_t)s0 * 32 + lane]);
            uint32_t u1 = __ldg(&hin[(size_t)s1 * 32 + lane]);
            uint32_t u2 = __ldg(&hin[(size_t)s2 * 32 + lane]);
            uint32_t u3 = __ldg(&hin[(size_t)s3 * 32 + lane]);
            float2 f0 = __bfloat1622float2(*(__nv_bfloat162*)&u0);
            float2 f1 = __bfloat1622float2(*(__nv_bfloat162*)&u1);
            float2 f2 = __bfloat1622float2(*(__nv_bfloat162*)&u2);
            float2 f3 = __bfloat1622float2(*(__nv_bfloat162*)&u3);
            a0 += f0.x + f1.x + f2.x + f3.x;
            a1 += f0.y + f1.y + f2.y + f3.y;
        }
        for (; j < e2; j++) {
            int sn = __ldg(&g_csr[j]);
            uint32_t u = __ldg(&hin[(size_t)sn * 32 + lane]);
            float2 f = __bfloat1622float2(*(__nv_bfloat162*)&u);
            a0 += f.x; a1 += f.y;
        }
        int cnt = e2 - s;
        float inv = (cnt > 0) ? (1.f / (float)cnt) : 0.f;
        __nv_bfloat162 p = __floats2bfloat162_rn(a0 * inv, a1 * inv);
        g_Zp[zbase + r * 32 + lane] = *(uint32_t*)&p;
    }
}

// ---------------- bf16 tensor-core layer GEMM ----------------
// out[n][64] = Z[n][0:256] @ w + h[n][0:64] @ root + bias  (all bf16 in, fp32 acc)
__device__ __forceinline__ void mma_bf16(float* d,
                                         uint32_t a0, uint32_t a1, uint32_t a2, uint32_t a3,
                                         uint32_t b0, uint32_t b1) {
    asm volatile(
        "mma.sync.aligned.m16n8k16.row.col.f32.bf16.bf16.f32 "
        "{%0,%1,%2,%3}, {%4,%5,%6,%7}, {%8,%9}, {%0,%1,%2,%3};\n"
        : "+f"(d[0]), "+f"(d[1]), "+f"(d[2]), "+f"(d[3])
        : "r"(a0), "r"(a1), "r"(a2), "r"(a3), "r"(b0), "r"(b1));
}

#define AS_STRIDE 20   // uint32 units; bank = (20m + ct) % 32 conflict-free
#define BS_STRIDE 72   // uint32 units; bank = (8ct + 8nt + gr) % 32 conflict-free

__global__ __launch_bounds__(256) void k_gemm_tc(
        const uint32_t* __restrict__ hin,   // [n][32] packed
        const uint32_t* __restrict__ wpk,   // [160][64] packed (w ++ root)
        const float* __restrict__ bias,     // [64]
        uint32_t* __restrict__ hout,        // [n][32] packed
        int n, int doRelu) {
    __shared__ uint32_t As[128 * AS_STRIDE];  // [m][k2], k2 = 0..15 per chunk
    __shared__ uint32_t Bs[16 * BS_STRIDE];   // [k2][n]

    int n0   = blockIdx.x * 128;
    int tid  = threadIdx.x;
    int warp = tid >> 5, lane = tid & 31;
    int gr = lane >> 2, ct = lane & 3;
    int warpM = warp * 16;

    float acc[8][4];
    #pragma unroll
    for (int i = 0; i < 8; i++)
        #pragma unroll
        for (int j = 0; j < 4; j++) acc[i][j] = 0.f;

    for (int kt = 0; kt < 10; kt++) {
        const uint32_t* Aptr; int lda, kb2;
        if (kt < 8) { Aptr = g_Zp; lda = 128; kb2 = kt * 16; }
        else        { Aptr = hin;  lda = 32;  kb2 = (kt - 8) * 16; }
        const uint32_t* Bptr = wpk + kt * 16 * 64;

        // A tile: 128 rows x 16 uint32 = 512 uint4, 2 per thread
        #pragma unroll
        for (int it = 0; it < 2; it++) {
            int i = tid + it * 256;
            int r = i >> 2, c4 = i & 3;
            int row = n0 + r;
            uint4 v = make_uint4(0u, 0u, 0u, 0u);
            if (row < n) v = *(const uint4*)&Aptr[(size_t)row * lda + kb2 + c4 * 4];
            *(uint4*)&As[r * AS_STRIDE + c4 * 4] = v;
        }
        // B tile: 16 rows x 64 uint32 = 256 uint4, 1 per thread
        {
            int r = tid >> 4, c4 = tid & 15;
            uint4 v = *(const uint4*)&Bptr[r * 64 + c4 * 4];
            *(uint4*)&Bs[r * BS_STRIDE + c4 * 4] = v;
        }
        __syncthreads();

        #pragma unroll
        for (int k16 = 0; k16 < 2; k16++) {
            int k2b = k16 * 8;
            uint32_t a0 = As[(warpM + gr)     * AS_STRIDE + k2b + ct];
            uint32_t a1 = As[(warpM + gr + 8) * AS_STRIDE + k2b + ct];
            uint32_t a2 = As[(warpM + gr)     * AS_STRIDE + k2b + ct + 4];
            uint32_t a3 = As[(warpM + gr + 8) * AS_STRIDE + k2b + ct + 4];
            #pragma unroll
            for (int nt = 0; nt < 8; nt++) {
                uint32_t b0 = Bs[(k2b + ct)     * BS_STRIDE + nt * 8 + gr];
                uint32_t b1 = Bs[(k2b + ct + 4) * BS_STRIDE + nt * 8 + gr];
                mma_bf16(acc[nt], a0, a1, a2, a3, b0, b1);
            }
        }
        __syncthreads();
    }

    // epilogue: bias, relu, pack to bf16, store
    int r0 = n0 + warpM + gr;
    int r1 = r0 + 8;
    #pragma unroll
    for (int nt = 0; nt < 8; nt++) {
        int col = nt * 8 + 2 * ct;
        float bb0 = bias[col], bb1 = bias[col + 1];
        float v00 = acc[nt][0] + bb0, v01 = acc[nt][1] + bb1;
        float v10 = acc[nt][2] + bb0, v11 = acc[nt][3] + bb1;
        if (doRelu) {
            v00 = fmaxf(v00, 0.f); v01 = fmaxf(v01, 0.f);
            v10 = fmaxf(v10, 0.f); v11 = fmaxf(v11, 0.f);
        }
        if (r0 < n) {
            __nv_bfloat162 p = __floats2bfloat162_rn(v00, v01);
            hout[(size_t)r0 * 32 + (col >> 1)] = *(uint32_t*)&p;
        }
        if (r1 < n) {
            __nv_bfloat162 p = __floats2bfloat162_rn(v10, v11);
            hout[(size_t)r1 * 32 + (col >> 1)] = *(uint32_t*)&p;
        }
    }
}

// ---------------- pooling (batch is sorted) ----------------
__device__ __forceinline__ int dev_lower_bound(const int* a, int n, int key) {
    int lo = 0, hi = n;
    while (lo < hi) { int mid = (lo + hi) >> 1; if (a[mid] < key) lo = mid + 1; else hi = mid; }
    return lo;
}

__global__ void k_pool(const uint32_t* __restrict__ h, const int* __restrict__ batch, int n) {
    int g = blockIdx.x;
    int lo = dev_lower_bound(batch, n, g);
    int hi = dev_lower_bound(batch, n, g + 1);
    __shared__ float sacc[8][64];
    int dp = threadIdx.x & 31, part = threadIdx.x >> 5;  // 256 threads: 8 parts x 32 pairs
    float s0 = 0.f, s1 = 0.f;
    for (int i = lo + part; i < hi; i += 8) {
        uint32_t u = h[(size_t)i * 32 + dp];
        float2 f = __bfloat1622float2(*(__nv_bfloat162*)&u);
        s0 += f.x; s1 += f.y;
    }
    sacc[part][dp * 2] = s0;
    sacc[part][dp * 2 + 1] = s1;
    __syncthreads();
    if (part < 2) {
        int d = part * 32 + dp + ((threadIdx.x >= 32) ? 0 : 0);
        // reduce 8 partials for dims [part*32 + dp] ... use 64 threads covering 64 dims
        d = part * 32 + dp;
        float tot = 0.f;
        #pragma unroll
        for (int p = 0; p < 8; p++) tot += sacc[p][d];
        float c = (float)(hi - lo);
        g_pooled[g * DDIM + d] = tot / fmaxf(c, 1.f);
    }
}

// ---------------- MLP head + log_softmax ----------------
__global__ void k_head(const float* __restrict__ fc1w, const float* __restrict__ fc1b,
                       const float* __restrict__ fc2w, const float* __restrict__ fc2b,
                       float* __restrict__ out) {
    __shared__ float w1s[64 * 64];
    for (int i = threadIdx.x; i < 64 * 64; i += 64) w1s[i] = fc1w[i];
    __syncthreads();
    int g = threadIdx.x;
    float p[64];
    #pragma unroll
    for (int d = 0; d < 64; d++) p[d] = g_pooled[g * 64 + d];
    float hid[64];
    #pragma unroll 4
    for (int e = 0; e < 64; e++) {
        float s = fc1b[e];
        #pragma unroll
        for (int d = 0; d < 64; d++) s += p[d] * w1s[d * 64 + e];
        hid[e] = fmaxf(s, 0.f);
    }
    float lg[CC];
    #pragma unroll
    for (int c = 0; c < CC; c++) {
        float s = fc2b[c];
        #pragma unroll 4
        for (int e = 0; e < 64; e++) s += hid[e] * fc2w[e * CC + c];
        lg[c] = s;
    }
    float m = lg[0];
    #pragma unroll
    for (int c = 1; c < CC; c++) m = fmaxf(m, lg[c]);
    float sum = 0.f;
    #pragma unroll
    for (int c = 0; c < CC; c++) sum += expf(lg[c] - m);
    float lse = logf(sum);
    #pragma unroll
    for (int c = 0; c < CC; c++) out[g * CC + c] = lg[c] - m - lse;
}

// ---------------- launch ----------------
extern "C" void kernel_launch(void* const* d_in, const int* in_sizes, int n_in,
                              void* d_out, int out_size) {
    const int*   x_op    = (const int*)  d_in[0];
    const int*   x_cat   = (const int*)  d_in[1];
    const int*   eidx    = (const int*)  d_in[2];
    const int*   etype   = (const int*)  d_in[3];
    const int*   batch   = (const int*)  d_in[4];
    const float* op_emb  = (const float*)d_in[5];
    const float* cat_emb = (const float*)d_in[6];
    const float* w1 = (const float*)d_in[7],  *r1 = (const float*)d_in[8],  *b1 = (const float*)d_in[9];
    const float* w2 = (const float*)d_in[10], *r2 = (const float*)d_in[11], *b2 = (const float*)d_in[12];
    const float* w3 = (const float*)d_in[13], *r3 = (const float*)d_in[14], *b3 = (const float*)d_in[15];
    const float* fc1w = (const float*)d_in[16], *fc1b = (const float*)d_in[17];
    const float* fc2w = (const float*)d_in[18], *fc2b = (const float*)d_in[19];
    float* out = (float*)d_out;

    int n = in_sizes[0];
    int E = in_sizes[3];
    const int* src = eidx;
    const int* tgt = eidx + E;

    uint32_t* hA;  cudaGetSymbolAddress((void**)&hA, g_hA);
    uint32_t* hB;  cudaGetSymbolAddress((void**)&hB, g_hB);
    uint32_t* Wpk; cudaGetSymbolAddress((void**)&Wpk, g_Wpk);

    int NB = (NR + SCAN_E - 1) / SCAN_E;  // 196

    // CSR build (reused across all 3 layers)
    k_zero_cnt<<<(NR + 255) / 256, 256>>>();
    k_count_edges<<<(E + 255) / 256, 256>>>(tgt, etype, E);
    k_scan1<<<NB, SCAN_T>>>();
    k_scan2<<<1, 256>>>(NB);
    k_scan3<<<NB, SCAN_T>>>(E);
    k_fill_edges<<<(E + 255) / 256, 256>>>(src, tgt, etype, E);

    // pack weights + embedding
    k_pack_weights<<<(3 * 160 * 64 + 255) / 256, 256>>>(w1, r1, w2, r2, w3, r3);
    k_embed<<<(n * 32 + 255) / 256, 256>>>(x_op, x_cat, op_emb, cat_emb, hA, n);

    int aggBlocks  = (n + 7) / 8;
    int gemmBlocks = (n + 127) / 128;

    // layer 1: hA -> hB (relu)
    k_agg<<<aggBlocks, 256>>>(hA, n);
    k_gemm_tc<<<gemmBlocks, 256>>>(hA, Wpk + 0 * 160 * 64, b1, hB, n, 1);
    // layer 2: hB -> hA (relu)
    k_agg<<<aggBlocks, 256>>>(hB, n);
    k_gemm_tc<<<gemmBlocks, 256>>>(hB, Wpk + 1 * 160 * 64, b2, hA, n, 1);
    // layer 3: hA -> hB (no relu)
    k_agg<<<aggBlocks, 256>>>(hA, n);
    k_gemm_tc<<<gemmBlocks, 256>>>(hA, Wpk + 2 * 160 * 64, b3, hB, n, 0);

    // pool + head
    k_pool<<<GG, 256>>>(hB, batch, n);
    k_head<<<1, 64>>>(fc1w, fc1b, fc2w, fc2b, out);
}